// round 13
// baseline (speedup 1.0000x reference)
#include <cuda_runtime.h>

#define N_NODES 12288
#define FDIM    32

// Scratch. Zero-initialized at module load; k_final re-zeros g_deg after use
// (graph-replay safe). g_inv / g_ya are rewritten identically each launch.
// The big accumulator is GONE: k_edge reds directly into d_out, which k_front
// zero-fills in parallel blocks.
__device__ __align__(16) float g_deg[N_NODES];   // raw degree (sum of attr per row)
__device__            int   g_inv[N_NODES];      // node -> perm idx + 1 (0 = absent)
__device__ __align__(16) float g_ya [N_NODES];   // raw atte scatter

#define OUT_F4   ((N_NODES * (FDIM + 1)) / 4)    // 101376 float4 in d_out

// ---------------------------------------------------------------------------
// K_front: three independent block ranges.
//   [0, ZB):          zero d_out (x region + atte region)
//   [ZB, ZB+EB):      deg[r] += attr[e], 2 edges/thread (int2+float2 loads)
//   [ZB+EB, +SB):     inverse-perm table + attention-coefficient scatter
__global__ void k_front(float* __restrict__ out,
                        const int* __restrict__ ei_row,
                        const float* __restrict__ attr, int nE,
                        const int* __restrict__ perm,
                        const float* __restrict__ coffe,
                        const int* __restrict__ bs_ptr,
                        int n_perm, int coffe_len, int ZB, int EB) {
    if (blockIdx.x < ZB) {
        int t = blockIdx.x * blockDim.x + threadIdx.x;
        if (t < OUT_F4)
            ((float4*)out)[t] = make_float4(0.f, 0.f, 0.f, 0.f);
    } else if (blockIdx.x < ZB + EB) {
        int v = (blockIdx.x - ZB) * blockDim.x + threadIdx.x;  // pair index
        int e = v * 2;
        if (e + 1 < nE) {
            int2   r2 = ((const int2*)ei_row)[v];
            float2 a2 = ((const float2*)attr)[v];
            atomicAdd(&g_deg[r2.x], a2.x);
            atomicAdd(&g_deg[r2.y], a2.y);
        } else if (e < nE) {
            atomicAdd(&g_deg[ei_row[e]], attr[e]);
        }
    } else {
        int k = (blockIdx.x - ZB - EB) * blockDim.x + threadIdx.x;
        if (k < n_perm) {
            int node = perm[k];
            g_inv[node] = k + 1;
            int bs        = *bs_ptr;
            int node_num  = coffe_len / bs;     // 192
            int per_batch = n_perm / bs;        // win*node_num
            int b = k / per_batch;
            int n = k % node_num;
            g_ya[node] = coffe[b * node_num + n];
        }
    }
}

// ---------------------------------------------------------------------------
// K_edge: 8 threads per edge; reds go STRAIGHT into d_out.
//   out[r*32 + 4q .. +3] += attr * d[c] * fea[inv[c]-1, 4q:4q+4]
//   out[N*32 + r]        += attr * d[c] * ya[c]          (q == 0 lane)
// Columns absent from perm contribute exactly zero -> skipped entirely.
__global__ void k_edge(const int* __restrict__ ei_row,
                       const int* __restrict__ ei_col,
                       const float* __restrict__ attr,
                       const float* __restrict__ fea,
                       float* __restrict__ out, int nE) {
    int t = blockIdx.x * blockDim.x + threadIdx.x;
    int e = t >> 3;
    int q = t & 7;
    if (e >= nE) return;
    int c  = ei_col[e];
    int pk = g_inv[c];
    if (pk == 0) return;

    int   r = ei_row[e];
    float s = attr[e] * rsqrtf(g_deg[c] + 1.0f);   // attr * d[c]

    float4 v = ((const float4*)(fea + (size_t)(pk - 1) * FDIM))[q];
    v.x *= s; v.y *= s; v.z *= s; v.w *= s;

    float* dst = out + (size_t)r * FDIM + q * 4;
    asm volatile("red.global.add.v4.f32 [%0], {%1, %2, %3, %4};"
                 :: "l"(dst), "f"(v.x), "f"(v.y), "f"(v.z), "f"(v.w)
                 : "memory");

    if (q == 0) {
        atomicAdd(out + (size_t)N_NODES * FDIM + r, s * g_ya[c]);
    }
}

// ---------------------------------------------------------------------------
// K_final: in-place scale of d_out:
//   x[i]    = d[i] * (acc_in_out[i] + d[i] * x_zero[i])   (self-loop folded)
//   atte[i] = d[i] * (accA_in_out[i] + d[i] * ya[i])
// Also re-zeros g_deg for the next replay.
__global__ void k_final(const float* __restrict__ fea, float* __restrict__ out) {
    int t = blockIdx.x * blockDim.x + threadIdx.x;
    int i = t >> 3;
    int q = t & 7;
    if (i >= N_NODES) return;
    float di = rsqrtf(g_deg[i] + 1.0f);
    int   pk = g_inv[i];

    float4 y = make_float4(0.f, 0.f, 0.f, 0.f);
    if (pk) y = ((const float4*)(fea + (size_t)(pk - 1) * FDIM))[q];

    float4* slot = (float4*)out + (size_t)i * (FDIM / 4) + q;
    float4 acc = *slot;
    float4 o;
    o.x = di * fmaf(di, y.x, acc.x);
    o.y = di * fmaf(di, y.y, acc.y);
    o.z = di * fmaf(di, y.z, acc.z);
    o.w = di * fmaf(di, y.w, acc.w);
    *slot = o;

    if (q == 0) {
        float ya = pk ? g_ya[i] : 0.f;
        float* aslot = out + (size_t)N_NODES * FDIM + i;
        *aslot = di * fmaf(di, ya, *aslot);
        g_deg[i] = 0.f;
    }
}

// ---------------------------------------------------------------------------
extern "C" void kernel_launch(void* const* d_in, const int* in_sizes, int n_in,
                              void* d_out, int out_size) {
    // metadata order:
    // 0: fea float32[6144,32]  1: perm int32[6144]  2: edge_index int32[2,393216]
    // 3: edge_attr float32[393216]  4: node_atte float32[1536]
    // 5: all_node_num int32[1]  6: batch_size int32[1]
    const float* fea    = (const float*)d_in[0];
    const int*   perm   = (const int*)  d_in[1];
    const int*   eidx   = (const int*)  d_in[2];
    const float* attr   = (const float*)d_in[3];
    const float* coffe  = (const float*)d_in[4];
    const int*   bs_ptr = (const int*)  d_in[6];

    const int n_perm    = in_sizes[1];
    const int nE        = in_sizes[3];
    const int coffe_len = in_sizes[4];
    const int* ei_row = eidx;
    const int* ei_col = eidx + nE;

    float* out = (float*)d_out;
    (void)out_size; (void)n_in;

    const int T  = 256;
    const int ZB = (OUT_F4 + T - 1) / T;             // zero-out blocks (396)
    const int nV = (nE + 1) / 2;                     // 2 edges per thread
    const int EB = (nV + T - 1) / T;                 // edge-degree blocks (768)
    const int SB = (n_perm + T - 1) / T;             // perm-scatter blocks (24)

    k_front<<<ZB + EB + SB, T>>>(out, ei_row, attr, nE, perm, coffe, bs_ptr,
                                 n_perm, coffe_len, ZB, EB);

    {
        long long nt = (long long)nE * 8;
        k_edge<<<(unsigned)((nt + T - 1) / T), T>>>(ei_row, ei_col, attr, fea,
                                                    out, nE);
    }

    k_final<<<(N_NODES * 8 + T - 1) / T, T>>>(fea, out);
}